// round 10
// baseline (speedup 1.0000x reference)
#include <cuda_runtime.h>
#include <cuda_bf16.h>
#include <math.h>
#include <stdint.h>

// Problem constants
#define BATCH 2
#define SEQ   2048
#define NTOK  4096
#define EMB   1024
#define HEADS 16
#define HDIM  64
#define FFDIM 4096

// ---------------------------------------------------------------------------
// Scratch buffers
// ---------------------------------------------------------------------------
__device__ float d_buf_h   [(size_t)NTOK * EMB];
__device__ float d_buf_qkv [(size_t)NTOK * 3 * EMB];
__device__ float d_buf_attn[(size_t)NTOK * EMB];
__device__ float d_buf_x1  [(size_t)NTOK * EMB];
__device__ float d_buf_ff1 [(size_t)NTOK * FFDIM];

// ---------------------------------------------------------------------------
// Helpers
// ---------------------------------------------------------------------------
__device__ __forceinline__ uint32_t smem_u32(const void* p) {
    uint32_t a;
    asm("{ .reg .u64 t; cvta.to.shared.u64 t, %1; cvt.u32.u64 %0, t; }"
        : "=r"(a) : "l"(p));
    return a;
}
__device__ __forceinline__ void cp_async16(uint32_t saddr, const void* gptr) {
    asm volatile("cp.async.cg.shared.global [%0], [%1], 16;"
                 :: "r"(saddr), "l"(gptr));
}
#define CP_COMMIT() asm volatile("cp.async.commit_group;" ::: "memory")
#define CP_WAIT(n)  asm volatile("cp.async.wait_group %0;" :: "n"(n) : "memory")

__device__ __forceinline__ uint32_t rna_tf32(float f) {
    uint32_t r;
    asm("cvt.rna.tf32.f32 %0, %1;" : "=r"(r) : "f"(f));
    return r;
}
__device__ __forceinline__ float rna_tf32_f(float f) {
    return __uint_as_float(rna_tf32(f));
}

__device__ __forceinline__ void mma_tf32(float& c0, float& c1, float& c2, float& c3,
                                         uint32_t a0, uint32_t a1, uint32_t a2, uint32_t a3,
                                         uint32_t b0, uint32_t b1)
{
    asm volatile(
        "mma.sync.aligned.m16n8k8.row.col.f32.tf32.tf32.f32 "
        "{%0,%1,%2,%3}, {%4,%5,%6,%7}, {%8,%9}, {%0,%1,%2,%3};"
        : "+f"(c0), "+f"(c1), "+f"(c2), "+f"(c3)
        : "r"(a0), "r"(a1), "r"(a2), "r"(a3), "r"(b0), "r"(b1));
}

__device__ __forceinline__ float gelu_exact(float v)
{
    return 0.5f * v * (1.0f + erff(v * 0.70710678118654752f));
}

// ---------------------------------------------------------------------------
// LayerNorm
// ---------------------------------------------------------------------------
__global__ __launch_bounds__(256)
void ln_kernel(const float* __restrict__ x, const float* __restrict__ gamma,
               const float* __restrict__ beta, float* __restrict__ y)
{
    const int row = blockIdx.x;
    const int t = threadIdx.x;
    const float4 v = ((const float4*)(x + (size_t)row * EMB))[t];
    __shared__ float sh[8];

    float s = v.x + v.y + v.z + v.w;
    #pragma unroll
    for (int o = 16; o; o >>= 1) s += __shfl_xor_sync(0xffffffffu, s, o);
    if ((t & 31) == 0) sh[t >> 5] = s;
    __syncthreads();
    float tot = 0.f;
    #pragma unroll
    for (int w = 0; w < 8; ++w) tot += sh[w];
    const float mu = tot * (1.0f / (float)EMB);

    const float dx0 = v.x - mu, dx1 = v.y - mu, dx2 = v.z - mu, dx3 = v.w - mu;
    float q = dx0*dx0 + dx1*dx1 + dx2*dx2 + dx3*dx3;
    __syncthreads();
    #pragma unroll
    for (int o = 16; o; o >>= 1) q += __shfl_xor_sync(0xffffffffu, q, o);
    if ((t & 31) == 0) sh[t >> 5] = q;
    __syncthreads();
    float tq = 0.f;
    #pragma unroll
    for (int w = 0; w < 8; ++w) tq += sh[w];
    const float rstd = rsqrtf(tq * (1.0f / (float)EMB) + 1e-5f);

    const float4 g4 = ((const float4*)gamma)[t];
    const float4 b4 = ((const float4*)beta)[t];
    float4 o4;
    o4.x = dx0 * rstd * g4.x + b4.x;
    o4.y = dx1 * rstd * g4.y + b4.y;
    o4.z = dx2 * rstd * g4.z + b4.z;
    o4.w = dx3 * rstd * g4.w + b4.w;
    ((float4*)(y + (size_t)row * EMB))[t] = o4;
}

// ---------------------------------------------------------------------------
// tf32 mma.sync GEMM: C[M,N] = A[M,K] @ W[N,K]^T + bias (+ epilogue)
// CTA tile 256x128, BK=16, 3-stage cp.async pipeline.
// 8 warps in 4x2 grid; warp tile 64x64 (4 mt x 8 nt of m16n8k8).
// ---------------------------------------------------------------------------
#define GBK     16
#define GSTR    20
#define AOPW    (256 * GSTR)          // A words per stage
#define BOPW    (128 * GSTR)          // B words per stage
#define STW     (AOPW + BOPW)
#define GSTAGES 3
#define GEMM_SMEM (GSTAGES * STW * 4)

__global__ __launch_bounds__(256, 1)
void tf32_gemm_kernel(const float* __restrict__ A, const float* __restrict__ W,
                      const float* __restrict__ bias, const float* __restrict__ res,
                      float* __restrict__ C, int M, int N, int K, int mode)
{
    extern __shared__ float smf[];
    const uint32_t sb = smem_u32(smf);
    const int tid = threadIdx.x;
    const int wid = tid >> 5;
    const int lane = tid & 31;
    const int gid = lane >> 2;
    const int tig = lane & 3;
    const int wrow = wid >> 1;        // 0..3 (64-row band)
    const int wcol = wid & 1;         // 0..1 (64-col band)
    const int row0 = blockIdx.y << 8;
    const int col0 = blockIdx.x << 7;
    const int nChunks = K >> 4;

    // cp.async geometry: A = 1024 float4 (4/thread), B = 512 float4 (2/thread)
    // idx = tid + 256*q ; row = idx>>2 ; seg = idx&3
    const float* aSrc[4];
    uint32_t aOff[4];
    #pragma unroll
    for (int q = 0; q < 4; ++q) {
        const int idx = tid + 256 * q;
        const int r = idx >> 2, seg = idx & 3;
        aSrc[q] = A + (size_t)(row0 + r) * K + seg * 4;
        aOff[q] = (r * GSTR + seg * 4) * 4;
    }
    const float* wSrc[2];
    uint32_t wOff[2];
    #pragma unroll
    for (int q = 0; q < 2; ++q) {
        const int idx = tid + 256 * q;
        const int r = idx >> 2, seg = idx & 3;
        wSrc[q] = W + (size_t)(col0 + r) * K + seg * 4;
        wOff[q] = (r * GSTR + seg * 4) * 4;
    }

    float acc[4][8][4];
    #pragma unroll
    for (int mt = 0; mt < 4; ++mt)
        #pragma unroll
        for (int nt = 0; nt < 8; ++nt)
            #pragma unroll
            for (int r = 0; r < 4; ++r) acc[mt][nt][r] = 0.f;

    // Prologue: issue chunks 0,1
    #pragma unroll
    for (int s = 0; s < 2; ++s) {
        const uint32_t stA = sb + s * STW * 4;
        const uint32_t stB = stA + AOPW * 4;
        const int k0 = s * GBK;
        #pragma unroll
        for (int q = 0; q < 4; ++q) cp_async16(stA + aOff[q], aSrc[q] + k0);
        #pragma unroll
        for (int q = 0; q < 2; ++q) cp_async16(stB + wOff[q], wSrc[q] + k0);
        CP_COMMIT();
    }

    const int aBaseRow = wrow * 64;   // + mt*16 + gid (+8)
    const int bBaseRow = wcol * 64;   // + nt*8 + gid

    for (int i = 0; i < nChunks; ++i) {
        const int j = i + 2;
        if (j < nChunks) {
            const int s = j % GSTAGES;
            const uint32_t stA = sb + s * STW * 4;
            const uint32_t stB = stA + AOPW * 4;
            const int k0 = j * GBK;
            #pragma unroll
            for (int q = 0; q < 4; ++q) cp_async16(stA + aOff[q], aSrc[q] + k0);
            #pragma unroll
            for (int q = 0; q < 2; ++q) cp_async16(stB + wOff[q], wSrc[q] + k0);
        }
        CP_COMMIT();
        CP_WAIT(2);
        __syncthreads();

        const float* As = smf + (i % GSTAGES) * STW;
        const float* Bs = As + AOPW;

        #pragma unroll
        for (int ks = 0; ks < 16; ks += 8) {
            uint32_t af[4][4], bf[8][2];
            #pragma unroll
            for (int mt = 0; mt < 4; ++mt) {
                const int r = aBaseRow + mt * 16 + gid;
                af[mt][0] = rna_tf32(As[(r    ) * GSTR + ks + tig    ]);
                af[mt][1] = rna_tf32(As[(r + 8) * GSTR + ks + tig    ]);
                af[mt][2] = rna_tf32(As[(r    ) * GSTR + ks + tig + 4]);
                af[mt][3] = rna_tf32(As[(r + 8) * GSTR + ks + tig + 4]);
            }
            #pragma unroll
            for (int nt = 0; nt < 8; ++nt) {
                const int r = bBaseRow + nt * 8 + gid;
                bf[nt][0] = rna_tf32(Bs[r * GSTR + ks + tig    ]);
                bf[nt][1] = rna_tf32(Bs[r * GSTR + ks + tig + 4]);
            }
            #pragma unroll
            for (int mt = 0; mt < 4; ++mt)
                #pragma unroll
                for (int nt = 0; nt < 8; ++nt)
                    mma_tf32(acc[mt][nt][0], acc[mt][nt][1],
                             acc[mt][nt][2], acc[mt][nt][3],
                             af[mt][0], af[mt][1], af[mt][2], af[mt][3],
                             bf[nt][0], bf[nt][1]);
        }
        __syncthreads();
    }

    // Epilogue
    #pragma unroll
    for (int mt = 0; mt < 4; ++mt) {
        #pragma unroll
        for (int half = 0; half < 2; ++half) {
            const int r = row0 + wrow * 64 + mt * 16 + gid + half * 8;
            float* Crow = C + (size_t)r * N;
            const float* Rrow = res + (size_t)r * N;
            #pragma unroll
            for (int nt = 0; nt < 8; ++nt) {
                const int c = col0 + wcol * 64 + nt * 8 + 2 * tig;
                float o0 = acc[mt][nt][half * 2 + 0] + bias[c];
                float o1 = acc[mt][nt][half * 2 + 1] + bias[c + 1];
                if (mode == 1) {
                    o0 = gelu_exact(o0); o1 = gelu_exact(o1);
                } else if (mode == 2) {
                    const float2 rv = *(const float2*)(Rrow + c);
                    o0 += rv.x; o1 += rv.y;
                }
                float2 ov; ov.x = o0; ov.y = o1;
                *(float2*)(Crow + c) = ov;
            }
        }
    }
}

// ---------------------------------------------------------------------------
// Flash attention with tf32 mma.sync (as R8, passing)
// ---------------------------------------------------------------------------
#define ASTR 68
#define A_QP 0
#define A_KS (128 * ASTR)
#define A_VT (A_KS + 64 * ASTR)
#define ATTN_SMEM ((128 * ASTR + 64 * ASTR + 64 * ASTR) * 4)

__global__ __launch_bounds__(256, 2)
void attn_mma_kernel(const float* __restrict__ qkv, float* __restrict__ out)
{
    extern __shared__ float sm[];
    float* Qs = sm + A_QP;
    float* Ps = sm + A_QP;
    float* Ks = sm + A_KS;
    float* Vt = sm + A_VT;
    const uint32_t sb = smem_u32(sm);

    const int tid  = threadIdx.x;
    const int wid  = tid >> 5;
    const int lane = tid & 31;
    const int gid  = lane >> 2;
    const int tig  = lane & 3;
    const int qt   = blockIdx.x;
    const int b    = blockIdx.y >> 4;
    const int h    = blockIdx.y & 15;

    const int ldr = tid >> 2;
    const int ldc = tid & 3;

    {
        const float* q0 = qkv + ((size_t)(b * SEQ + qt * 128 + ldr)) * (3 * EMB)
                              + h * HDIM + ldc * 16;
        const float* q1 = q0 + (size_t)64 * (3 * EMB);
        #pragma unroll
        for (int jj = 0; jj < 4; ++jj) {
            cp_async16(sb + (A_QP + ldr * ASTR + ldc * 16 + jj * 4) * 4,
                       q0 + jj * 4);
            cp_async16(sb + (A_QP + (ldr + 64) * ASTR + ldc * 16 + jj * 4) * 4,
                       q1 + jj * 4);
        }
        CP_COMMIT();
        CP_WAIT(0);
    }
    __syncthreads();

    uint32_t qa[8][4];
    {
        const int r0 = wid * 16 + gid;
        #pragma unroll
        for (int ks = 0; ks < 8; ++ks) {
            qa[ks][0] = rna_tf32(Qs[(r0    ) * ASTR + ks * 8 + tig    ]);
            qa[ks][1] = rna_tf32(Qs[(r0 + 8) * ASTR + ks * 8 + tig    ]);
            qa[ks][2] = rna_tf32(Qs[(r0    ) * ASTR + ks * 8 + tig + 4]);
            qa[ks][3] = rna_tf32(Qs[(r0 + 8) * ASTR + ks * 8 + tig + 4]);
        }
    }

    float m_r[2] = {-1e30f, -1e30f};
    float l_r[2] = {0.f, 0.f};
    float oacc[8][4];
    #pragma unroll
    for (int nt = 0; nt < 8; ++nt)
        #pragma unroll
        for (int r = 0; r < 4; ++r) oacc[nt][r] = 0.f;

    const float* kBase = qkv + ((size_t)(b * SEQ + ldr)) * (3 * EMB)
                             + EMB + h * HDIM;
    const float* vBase = kBase + EMB;

    for (int kt = 0; kt < SEQ / 64; ++kt) {
        __syncthreads();

        {
            const float* kg = kBase + (size_t)kt * 64 * (3 * EMB) + ldc * 16;
            #pragma unroll
            for (int jj = 0; jj < 4; ++jj)
                cp_async16(sb + (A_KS + ldr * ASTR + ldc * 16 + jj * 4) * 4,
                           kg + jj * 4);
        }
        const float* vg = vBase + (size_t)kt * 64 * (3 * EMB);
        float4 vv[4];
        #pragma unroll
        for (int jj = 0; jj < 4; ++jj)
            vv[jj] = *(const float4*)(vg + ldc * 16 + jj * 4);
        CP_COMMIT();
        CP_WAIT(0);
        #pragma unroll
        for (int jj = 0; jj < 4; ++jj) {
            const int d0 = ldc * 16 + jj * 4;
            Vt[(d0 + 0) * ASTR + ldr] = rna_tf32_f(vv[jj].x);
            Vt[(d0 + 1) * ASTR + ldr] = rna_tf32_f(vv[jj].y);
            Vt[(d0 + 2) * ASTR + ldr] = rna_tf32_f(vv[jj].z);
            Vt[(d0 + 3) * ASTR + ldr] = rna_tf32_f(vv[jj].w);
        }
        __syncthreads();

        float sacc[8][4];
        #pragma unroll
        for (int nt = 0; nt < 8; ++nt)
            #pragma unroll
            for (int r = 0; r < 4; ++r) sacc[nt][r] = 0.f;

        #pragma unroll
        for (int ks = 0; ks < 8; ++ks) {
            #pragma unroll
            for (int nt = 0; nt < 8; ++nt) {
                const int kr = nt * 8 + gid;
                const uint32_t b0 = rna_tf32(Ks[kr * ASTR + ks * 8 + tig    ]);
                const uint32_t b1 = rna_tf32(Ks[kr * ASTR + ks * 8 + tig + 4]);
                mma_tf32(sacc[nt][0], sacc[nt][1], sacc[nt][2], sacc[nt][3],
                         qa[ks][0], qa[ks][1], qa[ks][2], qa[ks][3], b0, b1);
            }
        }

        const int prow = wid * 16 + gid;
        #pragma unroll
        for (int hr = 0; hr < 2; ++hr) {
            float tm = -1e30f;
            #pragma unroll
            for (int nt = 0; nt < 8; ++nt) {
                sacc[nt][hr*2+0] *= 0.125f;
                sacc[nt][hr*2+1] *= 0.125f;
                tm = fmaxf(tm, fmaxf(sacc[nt][hr*2+0], sacc[nt][hr*2+1]));
            }
            tm = fmaxf(tm, __shfl_xor_sync(0xffffffffu, tm, 1));
            tm = fmaxf(tm, __shfl_xor_sync(0xffffffffu, tm, 2));
            const float mnew = fmaxf(m_r[hr], tm);
            const float alpha = __expf(m_r[hr] - mnew);
            float psum = 0.f;
            #pragma unroll
            for (int nt = 0; nt < 8; ++nt) {
                const float p0 = __expf(sacc[nt][hr*2+0] - mnew);
                const float p1 = __expf(sacc[nt][hr*2+1] - mnew);
                psum += p0 + p1;
                float2 pv;
                pv.x = rna_tf32_f(p0);
                pv.y = rna_tf32_f(p1);
                *(float2*)&Ps[(prow + hr * 8) * ASTR + nt * 8 + 2 * tig] = pv;
                oacc[nt][hr*2+0] *= alpha;
                oacc[nt][hr*2+1] *= alpha;
            }
            psum += __shfl_xor_sync(0xffffffffu, psum, 1);
            psum += __shfl_xor_sync(0xffffffffu, psum, 2);
            l_r[hr] = l_r[hr] * alpha + psum;
            m_r[hr] = mnew;
        }
        __syncthreads();

        #pragma unroll
        for (int ks = 0; ks < 8; ++ks) {
            uint32_t pa[4];
            pa[0] = __float_as_uint(Ps[(prow    ) * ASTR + ks * 8 + tig    ]);
            pa[1] = __float_as_uint(Ps[(prow + 8) * ASTR + ks * 8 + tig    ]);
            pa[2] = __float_as_uint(Ps[(prow    ) * ASTR + ks * 8 + tig + 4]);
            pa[3] = __float_as_uint(Ps[(prow + 8) * ASTR + ks * 8 + tig + 4]);
            #pragma unroll
            for (int nt = 0; nt < 8; ++nt) {
                const int dr = nt * 8 + gid;
                const uint32_t b0 = __float_as_uint(Vt[dr * ASTR + ks * 8 + tig    ]);
                const uint32_t b1 = __float_as_uint(Vt[dr * ASTR + ks * 8 + tig + 4]);
                mma_tf32(oacc[nt][0], oacc[nt][1], oacc[nt][2], oacc[nt][3],
                         pa[0], pa[1], pa[2], pa[3], b0, b1);
            }
        }
    }

    #pragma unroll
    for (int hr = 0; hr < 2; ++hr) {
        const float inv = 1.0f / l_r[hr];
        const int token = b * SEQ + qt * 128 + wid * 16 + gid + hr * 8;
        float* orow = out + (size_t)token * EMB + h * HDIM;
        #pragma unroll
        for (int nt = 0; nt < 8; ++nt) {
            float2 ov;
            ov.x = oacc[nt][hr*2+0] * inv;
            ov.y = oacc[nt][hr*2+1] * inv;
            *(float2*)(orow + nt * 8 + 2 * tig) = ov;
        }
    }
}

// ---------------------------------------------------------------------------
// Launch
// ---------------------------------------------------------------------------
extern "C" void kernel_launch(void* const* d_in, const int* in_sizes, int n_in,
                              void* d_out, int out_size)
{
    (void)in_sizes; (void)n_in; (void)out_size;
    const float* x     = (const float*)d_in[0];
    const float* qkv_w = (const float*)d_in[1];
    const float* qkv_b = (const float*)d_in[2];
    const float* out_w = (const float*)d_in[3];
    const float* out_b = (const float*)d_in[4];
    const float* ff1_w = (const float*)d_in[5];
    const float* ff1_b = (const float*)d_in[6];
    const float* ff2_w = (const float*)d_in[7];
    const float* ff2_b = (const float*)d_in[8];
    const float* ln1_g = (const float*)d_in[9];
    const float* ln1_b = (const float*)d_in[10];
    const float* ln2_g = (const float*)d_in[11];
    const float* ln2_b = (const float*)d_in[12];
    float* out = (float*)d_out;

    float *bh, *bqkv, *battn, *bx1, *bff1;
    cudaGetSymbolAddress((void**)&bh,    d_buf_h);
    cudaGetSymbolAddress((void**)&bqkv,  d_buf_qkv);
    cudaGetSymbolAddress((void**)&battn, d_buf_attn);
    cudaGetSymbolAddress((void**)&bx1,   d_buf_x1);
    cudaGetSymbolAddress((void**)&bff1,  d_buf_ff1);

    cudaFuncSetAttribute(attn_mma_kernel,
                         cudaFuncAttributeMaxDynamicSharedMemorySize, ATTN_SMEM);
    cudaFuncSetAttribute(tf32_gemm_kernel,
                         cudaFuncAttributeMaxDynamicSharedMemorySize, GEMM_SMEM);

    // 1. LN1
    ln_kernel<<<NTOK, 256>>>(x, ln1_g, ln1_b, bh);
    // 2. QKV projection: M=4096, N=3072, K=1024
    tf32_gemm_kernel<<<dim3(3 * EMB / 128, NTOK / 256), 256, GEMM_SMEM>>>(
        bh, qkv_w, qkv_b, nullptr, bqkv, NTOK, 3 * EMB, EMB, 0);
    // 3. Attention (tensor-core flash)
    attn_mma_kernel<<<dim3(SEQ / 128, BATCH * HEADS), 256, ATTN_SMEM>>>(bqkv, battn);
    // 4. Output projection + residual(x): M=4096, N=1024, K=1024
    tf32_gemm_kernel<<<dim3(EMB / 128, NTOK / 256), 256, GEMM_SMEM>>>(
        battn, out_w, out_b, x, bx1, NTOK, EMB, EMB, 2);
    // 5. LN2
    ln_kernel<<<NTOK, 256>>>(bx1, ln2_g, ln2_b, bh);
    // 6. FF1 + GELU: M=4096, N=4096, K=1024
    tf32_gemm_kernel<<<dim3(FFDIM / 128, NTOK / 256), 256, GEMM_SMEM>>>(
        bh, ff1_w, ff1_b, nullptr, bff1, NTOK, FFDIM, EMB, 1);
    // 7. FF2 + residual(x1): M=4096, N=1024, K=4096
    tf32_gemm_kernel<<<dim3(EMB / 128, NTOK / 256), 256, GEMM_SMEM>>>(
        bff1, ff2_w, ff2_b, bx1, out, NTOK, EMB, FFDIM, 2);
}

// round 14
// speedup vs baseline: 1.0710x; 1.0710x over previous
#include <cuda_runtime.h>
#include <cuda_bf16.h>
#include <math.h>
#include <stdint.h>

// Problem constants
#define BATCH 2
#define SEQ   2048
#define NTOK  4096
#define EMB   1024
#define HEADS 16
#define HDIM  64
#define FFDIM 4096

// ---------------------------------------------------------------------------
// Scratch buffers
// ---------------------------------------------------------------------------
__device__ float d_buf_h   [(size_t)NTOK * EMB];
__device__ float d_buf_qkv [(size_t)NTOK * 3 * EMB];
__device__ float d_buf_attn[(size_t)NTOK * EMB];
__device__ float d_buf_x1  [(size_t)NTOK * EMB];
__device__ float d_buf_ff1 [(size_t)NTOK * FFDIM];
// Pre-rounded (tf32-rna) weights
__device__ float d_w_qkv [(size_t)3 * EMB * EMB];
__device__ float d_w_out [(size_t)EMB * EMB];
__device__ float d_w_ff1 [(size_t)FFDIM * EMB];
__device__ float d_w_ff2 [(size_t)EMB * FFDIM];

// ---------------------------------------------------------------------------
// Helpers
// ---------------------------------------------------------------------------
__device__ __forceinline__ uint32_t smem_u32(const void* p) {
    uint32_t a;
    asm("{ .reg .u64 t; cvta.to.shared.u64 t, %1; cvt.u32.u64 %0, t; }"
        : "=r"(a) : "l"(p));
    return a;
}
__device__ __forceinline__ void cp_async16(uint32_t saddr, const void* gptr) {
    asm volatile("cp.async.cg.shared.global [%0], [%1], 16;"
                 :: "r"(saddr), "l"(gptr));
}
#define CP_COMMIT() asm volatile("cp.async.commit_group;" ::: "memory")
#define CP_WAIT(n)  asm volatile("cp.async.wait_group %0;" :: "n"(n) : "memory")

__device__ __forceinline__ uint32_t rna_tf32(float f) {
    uint32_t r;
    asm("cvt.rna.tf32.f32 %0, %1;" : "=r"(r) : "f"(f));
    return r;
}
__device__ __forceinline__ float rna_tf32_f(float f) {
    return __uint_as_float(rna_tf32(f));
}

__device__ __forceinline__ void mma_tf32(float& c0, float& c1, float& c2, float& c3,
                                         uint32_t a0, uint32_t a1, uint32_t a2, uint32_t a3,
                                         uint32_t b0, uint32_t b1)
{
    asm volatile(
        "mma.sync.aligned.m16n8k8.row.col.f32.tf32.tf32.f32 "
        "{%0,%1,%2,%3}, {%4,%5,%6,%7}, {%8,%9}, {%0,%1,%2,%3};"
        : "+f"(c0), "+f"(c1), "+f"(c2), "+f"(c3)
        : "r"(a0), "r"(a1), "r"(a2), "r"(a3), "r"(b0), "r"(b1));
}

__device__ __forceinline__ float gelu_exact(float v)
{
    return 0.5f * v * (1.0f + erff(v * 0.70710678118654752f));
}

// ---------------------------------------------------------------------------
// Elementwise tf32-rna rounding (weight pre-pass)
// ---------------------------------------------------------------------------
__global__ __launch_bounds__(256)
void round_kernel(const float4* __restrict__ in, float4* __restrict__ out, int n4)
{
    const int i = blockIdx.x * 256 + threadIdx.x;
    if (i < n4) {
        float4 v = in[i];
        v.x = rna_tf32_f(v.x); v.y = rna_tf32_f(v.y);
        v.z = rna_tf32_f(v.z); v.w = rna_tf32_f(v.w);
        out[i] = v;
    }
}

// ---------------------------------------------------------------------------
// LayerNorm — output rounded to tf32 (feeds GEMM A operand only)
// ---------------------------------------------------------------------------
__global__ __launch_bounds__(256)
void ln_kernel(const float* __restrict__ x, const float* __restrict__ gamma,
               const float* __restrict__ beta, float* __restrict__ y)
{
    const int row = blockIdx.x;
    const int t = threadIdx.x;
    const float4 v = ((const float4*)(x + (size_t)row * EMB))[t];
    __shared__ float sh[8];

    float s = v.x + v.y + v.z + v.w;
    #pragma unroll
    for (int o = 16; o; o >>= 1) s += __shfl_xor_sync(0xffffffffu, s, o);
    if ((t & 31) == 0) sh[t >> 5] = s;
    __syncthreads();
    float tot = 0.f;
    #pragma unroll
    for (int w = 0; w < 8; ++w) tot += sh[w];
    const float mu = tot * (1.0f / (float)EMB);

    const float dx0 = v.x - mu, dx1 = v.y - mu, dx2 = v.z - mu, dx3 = v.w - mu;
    float q = dx0*dx0 + dx1*dx1 + dx2*dx2 + dx3*dx3;
    __syncthreads();
    #pragma unroll
    for (int o = 16; o; o >>= 1) q += __shfl_xor_sync(0xffffffffu, q, o);
    if ((t & 31) == 0) sh[t >> 5] = q;
    __syncthreads();
    float tq = 0.f;
    #pragma unroll
    for (int w = 0; w < 8; ++w) tq += sh[w];
    const float rstd = rsqrtf(tq * (1.0f / (float)EMB) + 1e-5f);

    const float4 g4 = ((const float4*)gamma)[t];
    const float4 b4 = ((const float4*)beta)[t];
    float4 o4;
    o4.x = rna_tf32_f(dx0 * rstd * g4.x + b4.x);
    o4.y = rna_tf32_f(dx1 * rstd * g4.y + b4.y);
    o4.z = rna_tf32_f(dx2 * rstd * g4.z + b4.z);
    o4.w = rna_tf32_f(dx3 * rstd * g4.w + b4.w);
    ((float4*)(y + (size_t)row * EMB))[t] = o4;
}

// ---------------------------------------------------------------------------
// tf32 mma.sync GEMM: C[M,N] = A[M,K] @ W[N,K]^T + bias (+ epilogue)
// Operands are PRE-ROUNDED to tf32 — plain fragment loads, no cvt.
// 128x128 CTA tile, BK=16, 3-stage cp.async; 8 warps, warp tile 64x32.
// modes: 0 = bias, round output ; 1 = bias+GELU, round output ;
//        2 = bias+residual (full fp32 output)
// ---------------------------------------------------------------------------
#define GBK     16
#define GSTR    20
#define OPW     (128 * GSTR)
#define STW     (2 * OPW)
#define GSTAGES 3
#define GEMM_SMEM (GSTAGES * STW * 4)

__global__ __launch_bounds__(256, 2)
void tf32_gemm_kernel(const float* __restrict__ A, const float* __restrict__ W,
                      const float* __restrict__ bias, const float* __restrict__ res,
                      float* __restrict__ C, int M, int N, int K, int mode)
{
    extern __shared__ float smf[];
    const uint32_t sb = smem_u32(smf);
    const int tid = threadIdx.x;
    const int wid = tid >> 5;
    const int lane = tid & 31;
    const int gid = lane >> 2;
    const int tig = lane & 3;
    const int wrow = wid >> 2;
    const int wcol = wid & 3;
    const int row0 = blockIdx.y << 7;
    const int col0 = blockIdx.x << 7;
    const int nChunks = K >> 4;

    const int ldr = tid >> 2;
    const int ldc = tid & 3;
    const float* aSrc0 = A + (size_t)(row0 + ldr) * K + ldc * 4;
    const float* aSrc1 = A + (size_t)(row0 + ldr + 64) * K + ldc * 4;
    const float* wSrc0 = W + (size_t)(col0 + ldr) * K + ldc * 4;
    const float* wSrc1 = W + (size_t)(col0 + ldr + 64) * K + ldc * 4;
    const uint32_t dA0 = (ldr * GSTR + ldc * 4) * 4;
    const uint32_t dA1 = ((ldr + 64) * GSTR + ldc * 4) * 4;

    float acc[4][4][4];
    #pragma unroll
    for (int mt = 0; mt < 4; ++mt)
        #pragma unroll
        for (int nt = 0; nt < 4; ++nt)
            #pragma unroll
            for (int r = 0; r < 4; ++r) acc[mt][nt][r] = 0.f;

    #pragma unroll
    for (int s = 0; s < 2; ++s) {
        const uint32_t stA = sb + s * STW * 4;
        const uint32_t stB = stA + OPW * 4;
        const int k0 = s * GBK;
        cp_async16(stA + dA0, aSrc0 + k0);
        cp_async16(stA + dA1, aSrc1 + k0);
        cp_async16(stB + dA0, wSrc0 + k0);
        cp_async16(stB + dA1, wSrc1 + k0);
        CP_COMMIT();
    }

    const int aBaseRow = wrow * 64;
    const int bBaseRow = wcol * 32;

    for (int i = 0; i < nChunks; ++i) {
        const int j = i + 2;
        if (j < nChunks) {
            const int s = j % GSTAGES;
            const uint32_t stA = sb + s * STW * 4;
            const uint32_t stB = stA + OPW * 4;
            const int k0 = j * GBK;
            cp_async16(stA + dA0, aSrc0 + k0);
            cp_async16(stA + dA1, aSrc1 + k0);
            cp_async16(stB + dA0, wSrc0 + k0);
            cp_async16(stB + dA1, wSrc1 + k0);
        }
        CP_COMMIT();
        CP_WAIT(2);
        __syncthreads();

        const float* As = smf + (i % GSTAGES) * STW;
        const float* Bs = As + OPW;

        #pragma unroll
        for (int ks = 0; ks < 16; ks += 8) {
            uint32_t af[4][4], bf[4][2];
            #pragma unroll
            for (int mt = 0; mt < 4; ++mt) {
                const int r = aBaseRow + mt * 16 + gid;
                af[mt][0] = __float_as_uint(As[(r    ) * GSTR + ks + tig    ]);
                af[mt][1] = __float_as_uint(As[(r + 8) * GSTR + ks + tig    ]);
                af[mt][2] = __float_as_uint(As[(r    ) * GSTR + ks + tig + 4]);
                af[mt][3] = __float_as_uint(As[(r + 8) * GSTR + ks + tig + 4]);
            }
            #pragma unroll
            for (int nt = 0; nt < 4; ++nt) {
                const int r = bBaseRow + nt * 8 + gid;
                bf[nt][0] = __float_as_uint(Bs[r * GSTR + ks + tig    ]);
                bf[nt][1] = __float_as_uint(Bs[r * GSTR + ks + tig + 4]);
            }
            #pragma unroll
            for (int mt = 0; mt < 4; ++mt)
                #pragma unroll
                for (int nt = 0; nt < 4; ++nt)
                    mma_tf32(acc[mt][nt][0], acc[mt][nt][1],
                             acc[mt][nt][2], acc[mt][nt][3],
                             af[mt][0], af[mt][1], af[mt][2], af[mt][3],
                             bf[nt][0], bf[nt][1]);
        }
        __syncthreads();
    }

    #pragma unroll
    for (int mt = 0; mt < 4; ++mt) {
        #pragma unroll
        for (int half = 0; half < 2; ++half) {
            const int r = row0 + wrow * 64 + mt * 16 + gid + half * 8;
            float* Crow = C + (size_t)r * N;
            const float* Rrow = res + (size_t)r * N;
            #pragma unroll
            for (int nt = 0; nt < 4; ++nt) {
                const int c = col0 + wcol * 32 + nt * 8 + 2 * tig;
                float o0 = acc[mt][nt][half * 2 + 0] + bias[c];
                float o1 = acc[mt][nt][half * 2 + 1] + bias[c + 1];
                if (mode == 1) {
                    o0 = rna_tf32_f(gelu_exact(o0));
                    o1 = rna_tf32_f(gelu_exact(o1));
                } else if (mode == 2) {
                    const float2 rv = *(const float2*)(Rrow + c);
                    o0 += rv.x; o1 += rv.y;
                } else {
                    o0 = rna_tf32_f(o0);
                    o1 = rna_tf32_f(o1);
                }
                float2 ov; ov.x = o0; ov.y = o1;
                *(float2*)(Crow + c) = ov;
            }
        }
    }
}

// ---------------------------------------------------------------------------
// Flash attention with tf32 mma.sync — inputs pre-rounded, plain loads.
// Output rounded (feeds out-proj GEMM A operand only).
// ---------------------------------------------------------------------------
#define ASTR 68
#define A_QP 0
#define A_KS (128 * ASTR)
#define A_VT (A_KS + 64 * ASTR)
#define ATTN_SMEM ((128 * ASTR + 64 * ASTR + 64 * ASTR) * 4)

__global__ __launch_bounds__(256, 2)
void attn_mma_kernel(const float* __restrict__ qkv, float* __restrict__ out)
{
    extern __shared__ float sm[];
    float* Qs = sm + A_QP;
    float* Ps = sm + A_QP;
    float* Ks = sm + A_KS;
    float* Vt = sm + A_VT;
    const uint32_t sb = smem_u32(sm);

    const int tid  = threadIdx.x;
    const int wid  = tid >> 5;
    const int lane = tid & 31;
    const int gid  = lane >> 2;
    const int tig  = lane & 3;
    const int qt   = blockIdx.x;
    const int b    = blockIdx.y >> 4;
    const int h    = blockIdx.y & 15;

    const int ldr = tid >> 2;
    const int ldc = tid & 3;

    {
        const float* q0 = qkv + ((size_t)(b * SEQ + qt * 128 + ldr)) * (3 * EMB)
                              + h * HDIM + ldc * 16;
        const float* q1 = q0 + (size_t)64 * (3 * EMB);
        #pragma unroll
        for (int jj = 0; jj < 4; ++jj) {
            cp_async16(sb + (A_QP + ldr * ASTR + ldc * 16 + jj * 4) * 4,
                       q0 + jj * 4);
            cp_async16(sb + (A_QP + (ldr + 64) * ASTR + ldc * 16 + jj * 4) * 4,
                       q1 + jj * 4);
        }
        CP_COMMIT();
        CP_WAIT(0);
    }
    __syncthreads();

    uint32_t qa[8][4];
    {
        const int r0 = wid * 16 + gid;
        #pragma unroll
        for (int ks = 0; ks < 8; ++ks) {
            qa[ks][0] = __float_as_uint(Qs[(r0    ) * ASTR + ks * 8 + tig    ]);
            qa[ks][1] = __float_as_uint(Qs[(r0 + 8) * ASTR + ks * 8 + tig    ]);
            qa[ks][2] = __float_as_uint(Qs[(r0    ) * ASTR + ks * 8 + tig + 4]);
            qa[ks][3] = __float_as_uint(Qs[(r0 + 8) * ASTR + ks * 8 + tig + 4]);
        }
    }

    float m_r[2] = {-1e30f, -1e30f};
    float l_r[2] = {0.f, 0.f};
    float oacc[8][4];
    #pragma unroll
    for (int nt = 0; nt < 8; ++nt)
        #pragma unroll
        for (int r = 0; r < 4; ++r) oacc[nt][r] = 0.f;

    const float* kBase = qkv + ((size_t)(b * SEQ + ldr)) * (3 * EMB)
                             + EMB + h * HDIM;
    const float* vBase = kBase + EMB;

    for (int kt = 0; kt < SEQ / 64; ++kt) {
        __syncthreads();

        {
            const float* kg = kBase + (size_t)kt * 64 * (3 * EMB) + ldc * 16;
            #pragma unroll
            for (int jj = 0; jj < 4; ++jj)
                cp_async16(sb + (A_KS + ldr * ASTR + ldc * 16 + jj * 4) * 4,
                           kg + jj * 4);
        }
        const float* vg = vBase + (size_t)kt * 64 * (3 * EMB);
        float4 vv[4];
        #pragma unroll
        for (int jj = 0; jj < 4; ++jj)
            vv[jj] = *(const float4*)(vg + ldc * 16 + jj * 4);
        CP_COMMIT();
        CP_WAIT(0);
        #pragma unroll
        for (int jj = 0; jj < 4; ++jj) {
            const int d0 = ldc * 16 + jj * 4;
            Vt[(d0 + 0) * ASTR + ldr] = vv[jj].x;
            Vt[(d0 + 1) * ASTR + ldr] = vv[jj].y;
            Vt[(d0 + 2) * ASTR + ldr] = vv[jj].z;
            Vt[(d0 + 3) * ASTR + ldr] = vv[jj].w;
        }
        __syncthreads();

        float sacc[8][4];
        #pragma unroll
        for (int nt = 0; nt < 8; ++nt)
            #pragma unroll
            for (int r = 0; r < 4; ++r) sacc[nt][r] = 0.f;

        #pragma unroll
        for (int ks = 0; ks < 8; ++ks) {
            #pragma unroll
            for (int nt = 0; nt < 8; ++nt) {
                const int kr = nt * 8 + gid;
                const uint32_t b0 = __float_as_uint(Ks[kr * ASTR + ks * 8 + tig    ]);
                const uint32_t b1 = __float_as_uint(Ks[kr * ASTR + ks * 8 + tig + 4]);
                mma_tf32(sacc[nt][0], sacc[nt][1], sacc[nt][2], sacc[nt][3],
                         qa[ks][0], qa[ks][1], qa[ks][2], qa[ks][3], b0, b1);
            }
        }

        const int prow = wid * 16 + gid;
        #pragma unroll
        for (int hr = 0; hr < 2; ++hr) {
            float tm = -1e30f;
            #pragma unroll
            for (int nt = 0; nt < 8; ++nt) {
                sacc[nt][hr*2+0] *= 0.125f;
                sacc[nt][hr*2+1] *= 0.125f;
                tm = fmaxf(tm, fmaxf(sacc[nt][hr*2+0], sacc[nt][hr*2+1]));
            }
            tm = fmaxf(tm, __shfl_xor_sync(0xffffffffu, tm, 1));
            tm = fmaxf(tm, __shfl_xor_sync(0xffffffffu, tm, 2));
            const float mnew = fmaxf(m_r[hr], tm);
            const float alpha = __expf(m_r[hr] - mnew);
            float psum = 0.f;
            #pragma unroll
            for (int nt = 0; nt < 8; ++nt) {
                const float p0 = __expf(sacc[nt][hr*2+0] - mnew);
                const float p1 = __expf(sacc[nt][hr*2+1] - mnew);
                psum += p0 + p1;
                float2 pv;
                pv.x = rna_tf32_f(p0);
                pv.y = rna_tf32_f(p1);
                *(float2*)&Ps[(prow + hr * 8) * ASTR + nt * 8 + 2 * tig] = pv;
                oacc[nt][hr*2+0] *= alpha;
                oacc[nt][hr*2+1] *= alpha;
            }
            psum += __shfl_xor_sync(0xffffffffu, psum, 1);
            psum += __shfl_xor_sync(0xffffffffu, psum, 2);
            l_r[hr] = l_r[hr] * alpha + psum;
            m_r[hr] = mnew;
        }
        __syncthreads();

        #pragma unroll
        for (int ks = 0; ks < 8; ++ks) {
            uint32_t pa[4];
            pa[0] = __float_as_uint(Ps[(prow    ) * ASTR + ks * 8 + tig    ]);
            pa[1] = __float_as_uint(Ps[(prow + 8) * ASTR + ks * 8 + tig    ]);
            pa[2] = __float_as_uint(Ps[(prow    ) * ASTR + ks * 8 + tig + 4]);
            pa[3] = __float_as_uint(Ps[(prow + 8) * ASTR + ks * 8 + tig + 4]);
            #pragma unroll
            for (int nt = 0; nt < 8; ++nt) {
                const int dr = nt * 8 + gid;
                const uint32_t b0 = __float_as_uint(Vt[dr * ASTR + ks * 8 + tig    ]);
                const uint32_t b1 = __float_as_uint(Vt[dr * ASTR + ks * 8 + tig + 4]);
                mma_tf32(oacc[nt][0], oacc[nt][1], oacc[nt][2], oacc[nt][3],
                         pa[0], pa[1], pa[2], pa[3], b0, b1);
            }
        }
    }

    #pragma unroll
    for (int hr = 0; hr < 2; ++hr) {
        const float inv = 1.0f / l_r[hr];
        const int token = b * SEQ + qt * 128 + wid * 16 + gid + hr * 8;
        float* orow = out + (size_t)token * EMB + h * HDIM;
        #pragma unroll
        for (int nt = 0; nt < 8; ++nt) {
            float2 ov;
            ov.x = rna_tf32_f(oacc[nt][hr*2+0] * inv);
            ov.y = rna_tf32_f(oacc[nt][hr*2+1] * inv);
            *(float2*)(orow + nt * 8 + 2 * tig) = ov;
        }
    }
}

// ---------------------------------------------------------------------------
// Launch
// ---------------------------------------------------------------------------
extern "C" void kernel_launch(void* const* d_in, const int* in_sizes, int n_in,
                              void* d_out, int out_size)
{
    (void)in_sizes; (void)n_in; (void)out_size;
    const float* x     = (const float*)d_in[0];
    const float* qkv_w = (const float*)d_in[1];
    const float* qkv_b = (const float*)d_in[2];
    const float* out_w = (const float*)d_in[3];
    const float* out_b = (const float*)d_in[4];
    const float* ff1_w = (const float*)d_in[5];
    const float* ff1_b = (const float*)d_in[6];
    const float* ff2_w = (const float*)d_in[7];
    const float* ff2_b = (const float*)d_in[8];
    const float* ln1_g = (const float*)d_in[9];
    const float* ln1_b = (const float*)d_in[10];
    const float* ln2_g = (const float*)d_in[11];
    const float* ln2_b = (const float*)d_in[12];
    float* out = (float*)d_out;

    float *bh, *bqkv, *battn, *bx1, *bff1;
    float *wqkv, *wout, *wff1, *wff2;
    cudaGetSymbolAddress((void**)&bh,    d_buf_h);
    cudaGetSymbolAddress((void**)&bqkv,  d_buf_qkv);
    cudaGetSymbolAddress((void**)&battn, d_buf_attn);
    cudaGetSymbolAddress((void**)&bx1,   d_buf_x1);
    cudaGetSymbolAddress((void**)&bff1,  d_buf_ff1);
    cudaGetSymbolAddress((void**)&wqkv,  d_w_qkv);
    cudaGetSymbolAddress((void**)&wout,  d_w_out);
    cudaGetSymbolAddress((void**)&wff1,  d_w_ff1);
    cudaGetSymbolAddress((void**)&wff2,  d_w_ff2);

    cudaFuncSetAttribute(attn_mma_kernel,
                         cudaFuncAttributeMaxDynamicSharedMemorySize, ATTN_SMEM);
    cudaFuncSetAttribute(tf32_gemm_kernel,
                         cudaFuncAttributeMaxDynamicSharedMemorySize, GEMM_SMEM);

    // 0. Pre-round weights to tf32 (one pass; removes cvts from GEMM hot loop)
    {
        const int n_qkv = 3 * EMB * EMB / 4, n_out = EMB * EMB / 4;
        const int n_ff  = FFDIM * EMB / 4;
        round_kernel<<<(n_qkv + 255) / 256, 256>>>((const float4*)qkv_w, (float4*)wqkv, n_qkv);
        round_kernel<<<(n_out + 255) / 256, 256>>>((const float4*)out_w, (float4*)wout, n_out);
        round_kernel<<<(n_ff  + 255) / 256, 256>>>((const float4*)ff1_w, (float4*)wff1, n_ff);
        round_kernel<<<(n_ff  + 255) / 256, 256>>>((const float4*)ff2_w, (float4*)wff2, n_ff);
    }

    // 1. LN1 (rounded output)
    ln_kernel<<<NTOK, 256>>>(x, ln1_g, ln1_b, bh);
    // 2. QKV projection (rounded output — feeds attention)
    tf32_gemm_kernel<<<dim3(3 * EMB / 128, NTOK / 128), 256, GEMM_SMEM>>>(
        bh, wqkv, qkv_b, nullptr, bqkv, NTOK, 3 * EMB, EMB, 0);
    // 3. Attention (tensor-core flash; rounded output)
    attn_mma_kernel<<<dim3(SEQ / 128, BATCH * HEADS), 256, ATTN_SMEM>>>(bqkv, battn);
    // 4. Output projection + residual(x) — full fp32 output
    tf32_gemm_kernel<<<dim3(EMB / 128, NTOK / 128), 256, GEMM_SMEM>>>(
        battn, wout, out_b, x, bx1, NTOK, EMB, EMB, 2);
    // 5. LN2 (rounded output)
    ln_kernel<<<NTOK, 256>>>(bx1, ln2_g, ln2_b, bh);
    // 6. FF1 + GELU (rounded output)
    tf32_gemm_kernel<<<dim3(FFDIM / 128, NTOK / 128), 256, GEMM_SMEM>>>(
        bh, wff1, ff1_b, nullptr, bff1, NTOK, FFDIM, EMB, 1);
    // 7. FF2 + residual(x1) — full fp32 output
    tf32_gemm_kernel<<<dim3(EMB / 128, NTOK / 128), 256, GEMM_SMEM>>>(
        bff1, wff2, ff2_b, bx1, out, NTOK, EMB, FFDIM, 2);
}

// round 15
// speedup vs baseline: 1.1944x; 1.1152x over previous
#include <cuda_runtime.h>
#include <cuda_bf16.h>
#include <math.h>
#include <stdint.h>

// Problem constants
#define BATCH 2
#define SEQ   2048
#define NTOK  4096
#define EMB   1024
#define HEADS 16
#define HDIM  64
#define FFDIM 4096

// ---------------------------------------------------------------------------
// Scratch buffers
// ---------------------------------------------------------------------------
__device__ float d_buf_h   [(size_t)NTOK * EMB];
__device__ float d_buf_qkv [(size_t)NTOK * 3 * EMB];
__device__ float d_buf_attn[(size_t)NTOK * EMB];
__device__ float d_buf_x1  [(size_t)NTOK * EMB];
__device__ float d_buf_ff1 [(size_t)NTOK * FFDIM];
// Pre-rounded (tf32-rna) weights
__device__ float d_w_qkv [(size_t)3 * EMB * EMB];
__device__ float d_w_out [(size_t)EMB * EMB];
__device__ float d_w_ff1 [(size_t)FFDIM * EMB];
__device__ float d_w_ff2 [(size_t)EMB * FFDIM];

// ---------------------------------------------------------------------------
// Helpers
// ---------------------------------------------------------------------------
__device__ __forceinline__ uint32_t smem_u32(const void* p) {
    uint32_t a;
    asm("{ .reg .u64 t; cvta.to.shared.u64 t, %1; cvt.u32.u64 %0, t; }"
        : "=r"(a) : "l"(p));
    return a;
}
__device__ __forceinline__ void cp_async16(uint32_t saddr, const void* gptr) {
    asm volatile("cp.async.cg.shared.global [%0], [%1], 16;"
                 :: "r"(saddr), "l"(gptr));
}
#define CP_COMMIT() asm volatile("cp.async.commit_group;" ::: "memory")
#define CP_WAIT(n)  asm volatile("cp.async.wait_group %0;" :: "n"(n) : "memory")

__device__ __forceinline__ uint32_t rna_tf32(float f) {
    uint32_t r;
    asm("cvt.rna.tf32.f32 %0, %1;" : "=r"(r) : "f"(f));
    return r;
}
__device__ __forceinline__ float rna_tf32_f(float f) {
    return __uint_as_float(rna_tf32(f));
}

__device__ __forceinline__ void mma_tf32(float& c0, float& c1, float& c2, float& c3,
                                         uint32_t a0, uint32_t a1, uint32_t a2, uint32_t a3,
                                         uint32_t b0, uint32_t b1)
{
    asm volatile(
        "mma.sync.aligned.m16n8k8.row.col.f32.tf32.tf32.f32 "
        "{%0,%1,%2,%3}, {%4,%5,%6,%7}, {%8,%9}, {%0,%1,%2,%3};"
        : "+f"(c0), "+f"(c1), "+f"(c2), "+f"(c3)
        : "r"(a0), "r"(a1), "r"(a2), "r"(a3), "r"(b0), "r"(b1));
}

__device__ __forceinline__ float gelu_exact(float v)
{
    return 0.5f * v * (1.0f + erff(v * 0.70710678118654752f));
}

// ---------------------------------------------------------------------------
// Elementwise tf32-rna rounding (weight pre-pass)
// ---------------------------------------------------------------------------
__global__ __launch_bounds__(256)
void round_kernel(const float4* __restrict__ in, float4* __restrict__ out, int n4)
{
    const int i = blockIdx.x * 256 + threadIdx.x;
    if (i < n4) {
        float4 v = in[i];
        v.x = rna_tf32_f(v.x); v.y = rna_tf32_f(v.y);
        v.z = rna_tf32_f(v.z); v.w = rna_tf32_f(v.w);
        out[i] = v;
    }
}

// ---------------------------------------------------------------------------
// LayerNorm — output rounded to tf32 (feeds GEMM A operand only)
// ---------------------------------------------------------------------------
__global__ __launch_bounds__(256)
void ln_kernel(const float* __restrict__ x, const float* __restrict__ gamma,
               const float* __restrict__ beta, float* __restrict__ y)
{
    const int row = blockIdx.x;
    const int t = threadIdx.x;
    const float4 v = ((const float4*)(x + (size_t)row * EMB))[t];
    __shared__ float sh[8];

    float s = v.x + v.y + v.z + v.w;
    #pragma unroll
    for (int o = 16; o; o >>= 1) s += __shfl_xor_sync(0xffffffffu, s, o);
    if ((t & 31) == 0) sh[t >> 5] = s;
    __syncthreads();
    float tot = 0.f;
    #pragma unroll
    for (int w = 0; w < 8; ++w) tot += sh[w];
    const float mu = tot * (1.0f / (float)EMB);

    const float dx0 = v.x - mu, dx1 = v.y - mu, dx2 = v.z - mu, dx3 = v.w - mu;
    float q = dx0*dx0 + dx1*dx1 + dx2*dx2 + dx3*dx3;
    __syncthreads();
    #pragma unroll
    for (int o = 16; o; o >>= 1) q += __shfl_xor_sync(0xffffffffu, q, o);
    if ((t & 31) == 0) sh[t >> 5] = q;
    __syncthreads();
    float tq = 0.f;
    #pragma unroll
    for (int w = 0; w < 8; ++w) tq += sh[w];
    const float rstd = rsqrtf(tq * (1.0f / (float)EMB) + 1e-5f);

    const float4 g4 = ((const float4*)gamma)[t];
    const float4 b4 = ((const float4*)beta)[t];
    float4 o4;
    o4.x = rna_tf32_f(dx0 * rstd * g4.x + b4.x);
    o4.y = rna_tf32_f(dx1 * rstd * g4.y + b4.y);
    o4.z = rna_tf32_f(dx2 * rstd * g4.z + b4.z);
    o4.w = rna_tf32_f(dx3 * rstd * g4.w + b4.w);
    ((float4*)(y + (size_t)row * EMB))[t] = o4;
}

// ---------------------------------------------------------------------------
// tf32 mma.sync GEMM: C[M,N] = A[M,K] @ W[N,K]^T + bias (+ epilogue)
// Operands PRE-ROUNDED to tf32 — plain fragment loads.
// 128x128 CTA tile, BK=16, 3-stage cp.async; 8 warps, warp tile 64x32.
// CUTLASS-style single barrier per chunk:
//   wait(1) -> __syncthreads -> [frag ks=0 | issue next-chunk cp.async |
//   MMA ks=0 | frag ks=8 | MMA ks=8]
// modes: 0 = bias, round output ; 1 = bias+GELU, round output ;
//        2 = bias+residual (full fp32 output)
// ---------------------------------------------------------------------------
#define GBK     16
#define GSTR    20
#define OPW     (128 * GSTR)
#define STW     (2 * OPW)
#define GSTAGES 3
#define GEMM_SMEM (GSTAGES * STW * 4)

__global__ __launch_bounds__(256, 2)
void tf32_gemm_kernel(const float* __restrict__ A, const float* __restrict__ W,
                      const float* __restrict__ bias, const float* __restrict__ res,
                      float* __restrict__ C, int M, int N, int K, int mode)
{
    extern __shared__ float smf[];
    const uint32_t sb = smem_u32(smf);
    const int tid = threadIdx.x;
    const int wid = tid >> 5;
    const int lane = tid & 31;
    const int gid = lane >> 2;
    const int tig = lane & 3;
    const int wrow = wid >> 2;
    const int wcol = wid & 3;
    const int row0 = blockIdx.y << 7;
    const int col0 = blockIdx.x << 7;
    const int nChunks = K >> 4;

    const int ldr = tid >> 2;
    const int ldc = tid & 3;
    const float* aSrc0 = A + (size_t)(row0 + ldr) * K + ldc * 4;
    const float* aSrc1 = A + (size_t)(row0 + ldr + 64) * K + ldc * 4;
    const float* wSrc0 = W + (size_t)(col0 + ldr) * K + ldc * 4;
    const float* wSrc1 = W + (size_t)(col0 + ldr + 64) * K + ldc * 4;
    const uint32_t dA0 = (ldr * GSTR + ldc * 4) * 4;
    const uint32_t dA1 = ((ldr + 64) * GSTR + ldc * 4) * 4;

    float acc[4][4][4];
    #pragma unroll
    for (int mt = 0; mt < 4; ++mt)
        #pragma unroll
        for (int nt = 0; nt < 4; ++nt)
            #pragma unroll
            for (int r = 0; r < 4; ++r) acc[mt][nt][r] = 0.f;

    // Prologue: issue chunks 0,1 (two cp.async groups)
    #pragma unroll
    for (int s = 0; s < 2; ++s) {
        const uint32_t stA = sb + s * STW * 4;
        const uint32_t stB = stA + OPW * 4;
        const int k0 = s * GBK;
        cp_async16(stA + dA0, aSrc0 + k0);
        cp_async16(stA + dA1, aSrc1 + k0);
        cp_async16(stB + dA0, wSrc0 + k0);
        cp_async16(stB + dA1, wSrc1 + k0);
        CP_COMMIT();
    }

    const int aBaseRow = wrow * 64;
    const int bBaseRow = wcol * 32;

    for (int i = 0; i < nChunks; ++i) {
        // chunk i resident (my copies done) ...
        CP_WAIT(1);
        // ... and everyone's copies visible; stage (i-1)%3 free for rewrite
        __syncthreads();

        const float* As = smf + (i % GSTAGES) * STW;
        const float* Bs = As + OPW;

        // ---- fragments for k-slice 0 ----
        uint32_t af0[4][4], bf0[4][2];
        #pragma unroll
        for (int mt = 0; mt < 4; ++mt) {
            const int r = aBaseRow + mt * 16 + gid;
            af0[mt][0] = __float_as_uint(As[(r    ) * GSTR + tig    ]);
            af0[mt][1] = __float_as_uint(As[(r + 8) * GSTR + tig    ]);
            af0[mt][2] = __float_as_uint(As[(r    ) * GSTR + tig + 4]);
            af0[mt][3] = __float_as_uint(As[(r + 8) * GSTR + tig + 4]);
        }
        #pragma unroll
        for (int nt = 0; nt < 4; ++nt) {
            const int r = bBaseRow + nt * 8 + gid;
            bf0[nt][0] = __float_as_uint(Bs[r * GSTR + tig    ]);
            bf0[nt][1] = __float_as_uint(Bs[r * GSTR + tig + 4]);
        }

        // ---- issue next chunk's loads (stage (i+2)%3 == (i-1)%3) ----
        const int j = i + 2;
        if (j < nChunks) {
            const int s = j % GSTAGES;
            const uint32_t stA = sb + s * STW * 4;
            const uint32_t stB = stA + OPW * 4;
            const int k0 = j * GBK;
            cp_async16(stA + dA0, aSrc0 + k0);
            cp_async16(stA + dA1, aSrc1 + k0);
            cp_async16(stB + dA0, wSrc0 + k0);
            cp_async16(stB + dA1, wSrc1 + k0);
        }
        CP_COMMIT();

        // ---- MMAs for k-slice 0 ----
        #pragma unroll
        for (int mt = 0; mt < 4; ++mt)
            #pragma unroll
            for (int nt = 0; nt < 4; ++nt)
                mma_tf32(acc[mt][nt][0], acc[mt][nt][1],
                         acc[mt][nt][2], acc[mt][nt][3],
                         af0[mt][0], af0[mt][1], af0[mt][2], af0[mt][3],
                         bf0[nt][0], bf0[nt][1]);

        // ---- fragments + MMAs for k-slice 1 ----
        uint32_t af1[4][4], bf1[4][2];
        #pragma unroll
        for (int mt = 0; mt < 4; ++mt) {
            const int r = aBaseRow + mt * 16 + gid;
            af1[mt][0] = __float_as_uint(As[(r    ) * GSTR + 8 + tig    ]);
            af1[mt][1] = __float_as_uint(As[(r + 8) * GSTR + 8 + tig    ]);
            af1[mt][2] = __float_as_uint(As[(r    ) * GSTR + 8 + tig + 4]);
            af1[mt][3] = __float_as_uint(As[(r + 8) * GSTR + 8 + tig + 4]);
        }
        #pragma unroll
        for (int nt = 0; nt < 4; ++nt) {
            const int r = bBaseRow + nt * 8 + gid;
            bf1[nt][0] = __float_as_uint(Bs[r * GSTR + 8 + tig    ]);
            bf1[nt][1] = __float_as_uint(Bs[r * GSTR + 8 + tig + 4]);
        }
        #pragma unroll
        for (int mt = 0; mt < 4; ++mt)
            #pragma unroll
            for (int nt = 0; nt < 4; ++nt)
                mma_tf32(acc[mt][nt][0], acc[mt][nt][1],
                         acc[mt][nt][2], acc[mt][nt][3],
                         af1[mt][0], af1[mt][1], af1[mt][2], af1[mt][3],
                         bf1[nt][0], bf1[nt][1]);
    }

    #pragma unroll
    for (int mt = 0; mt < 4; ++mt) {
        #pragma unroll
        for (int half = 0; half < 2; ++half) {
            const int r = row0 + wrow * 64 + mt * 16 + gid + half * 8;
            float* Crow = C + (size_t)r * N;
            const float* Rrow = res + (size_t)r * N;
            #pragma unroll
            for (int nt = 0; nt < 4; ++nt) {
                const int c = col0 + wcol * 32 + nt * 8 + 2 * tig;
                float o0 = acc[mt][nt][half * 2 + 0] + bias[c];
                float o1 = acc[mt][nt][half * 2 + 1] + bias[c + 1];
                if (mode == 1) {
                    o0 = rna_tf32_f(gelu_exact(o0));
                    o1 = rna_tf32_f(gelu_exact(o1));
                } else if (mode == 2) {
                    const float2 rv = *(const float2*)(Rrow + c);
                    o0 += rv.x; o1 += rv.y;
                } else {
                    o0 = rna_tf32_f(o0);
                    o1 = rna_tf32_f(o1);
                }
                float2 ov; ov.x = o0; ov.y = o1;
                *(float2*)(Crow + c) = ov;
            }
        }
    }
}

// ---------------------------------------------------------------------------
// Flash attention with tf32 mma.sync — inputs pre-rounded, plain loads.
// ---------------------------------------------------------------------------
#define ASTR 68
#define A_QP 0
#define A_KS (128 * ASTR)
#define A_VT (A_KS + 64 * ASTR)
#define ATTN_SMEM ((128 * ASTR + 64 * ASTR + 64 * ASTR) * 4)

__global__ __launch_bounds__(256, 2)
void attn_mma_kernel(const float* __restrict__ qkv, float* __restrict__ out)
{
    extern __shared__ float sm[];
    float* Qs = sm + A_QP;
    float* Ps = sm + A_QP;
    float* Ks = sm + A_KS;
    float* Vt = sm + A_VT;
    const uint32_t sb = smem_u32(sm);

    const int tid  = threadIdx.x;
    const int wid  = tid >> 5;
    const int lane = tid & 31;
    const int gid  = lane >> 2;
    const int tig  = lane & 3;
    const int qt   = blockIdx.x;
    const int b    = blockIdx.y >> 4;
    const int h    = blockIdx.y & 15;

    const int ldr = tid >> 2;
    const int ldc = tid & 3;

    {
        const float* q0 = qkv + ((size_t)(b * SEQ + qt * 128 + ldr)) * (3 * EMB)
                              + h * HDIM + ldc * 16;
        const float* q1 = q0 + (size_t)64 * (3 * EMB);
        #pragma unroll
        for (int jj = 0; jj < 4; ++jj) {
            cp_async16(sb + (A_QP + ldr * ASTR + ldc * 16 + jj * 4) * 4,
                       q0 + jj * 4);
            cp_async16(sb + (A_QP + (ldr + 64) * ASTR + ldc * 16 + jj * 4) * 4,
                       q1 + jj * 4);
        }
        CP_COMMIT();
        CP_WAIT(0);
    }
    __syncthreads();

    uint32_t qa[8][4];
    {
        const int r0 = wid * 16 + gid;
        #pragma unroll
        for (int ks = 0; ks < 8; ++ks) {
            qa[ks][0] = __float_as_uint(Qs[(r0    ) * ASTR + ks * 8 + tig    ]);
            qa[ks][1] = __float_as_uint(Qs[(r0 + 8) * ASTR + ks * 8 + tig    ]);
            qa[ks][2] = __float_as_uint(Qs[(r0    ) * ASTR + ks * 8 + tig + 4]);
            qa[ks][3] = __float_as_uint(Qs[(r0 + 8) * ASTR + ks * 8 + tig + 4]);
        }
    }

    float m_r[2] = {-1e30f, -1e30f};
    float l_r[2] = {0.f, 0.f};
    float oacc[8][4];
    #pragma unroll
    for (int nt = 0; nt < 8; ++nt)
        #pragma unroll
        for (int r = 0; r < 4; ++r) oacc[nt][r] = 0.f;

    const float* kBase = qkv + ((size_t)(b * SEQ + ldr)) * (3 * EMB)
                             + EMB + h * HDIM;
    const float* vBase = kBase + EMB;

    for (int kt = 0; kt < SEQ / 64; ++kt) {
        __syncthreads();

        {
            const float* kg = kBase + (size_t)kt * 64 * (3 * EMB) + ldc * 16;
            #pragma unroll
            for (int jj = 0; jj < 4; ++jj)
                cp_async16(sb + (A_KS + ldr * ASTR + ldc * 16 + jj * 4) * 4,
                           kg + jj * 4);
        }
        const float* vg = vBase + (size_t)kt * 64 * (3 * EMB);
        float4 vv[4];
        #pragma unroll
        for (int jj = 0; jj < 4; ++jj)
            vv[jj] = *(const float4*)(vg + ldc * 16 + jj * 4);
        CP_COMMIT();
        CP_WAIT(0);
        #pragma unroll
        for (int jj = 0; jj < 4; ++jj) {
            const int d0 = ldc * 16 + jj * 4;
            Vt[(d0 + 0) * ASTR + ldr] = vv[jj].x;
            Vt[(d0 + 1) * ASTR + ldr] = vv[jj].y;
            Vt[(d0 + 2) * ASTR + ldr] = vv[jj].z;
            Vt[(d0 + 3) * ASTR + ldr] = vv[jj].w;
        }
        __syncthreads();

        float sacc[8][4];
        #pragma unroll
        for (int nt = 0; nt < 8; ++nt)
            #pragma unroll
            for (int r = 0; r < 4; ++r) sacc[nt][r] = 0.f;

        #pragma unroll
        for (int ks = 0; ks < 8; ++ks) {
            #pragma unroll
            for (int nt = 0; nt < 8; ++nt) {
                const int kr = nt * 8 + gid;
                const uint32_t b0 = __float_as_uint(Ks[kr * ASTR + ks * 8 + tig    ]);
                const uint32_t b1 = __float_as_uint(Ks[kr * ASTR + ks * 8 + tig + 4]);
                mma_tf32(sacc[nt][0], sacc[nt][1], sacc[nt][2], sacc[nt][3],
                         qa[ks][0], qa[ks][1], qa[ks][2], qa[ks][3], b0, b1);
            }
        }

        const int prow = wid * 16 + gid;
        #pragma unroll
        for (int hr = 0; hr < 2; ++hr) {
            float tm = -1e30f;
            #pragma unroll
            for (int nt = 0; nt < 8; ++nt) {
                sacc[nt][hr*2+0] *= 0.125f;
                sacc[nt][hr*2+1] *= 0.125f;
                tm = fmaxf(tm, fmaxf(sacc[nt][hr*2+0], sacc[nt][hr*2+1]));
            }
            tm = fmaxf(tm, __shfl_xor_sync(0xffffffffu, tm, 1));
            tm = fmaxf(tm, __shfl_xor_sync(0xffffffffu, tm, 2));
            const float mnew = fmaxf(m_r[hr], tm);
            const float alpha = __expf(m_r[hr] - mnew);
            float psum = 0.f;
            #pragma unroll
            for (int nt = 0; nt < 8; ++nt) {
                const float p0 = __expf(sacc[nt][hr*2+0] - mnew);
                const float p1 = __expf(sacc[nt][hr*2+1] - mnew);
                psum += p0 + p1;
                float2 pv;
                pv.x = rna_tf32_f(p0);
                pv.y = rna_tf32_f(p1);
                *(float2*)&Ps[(prow + hr * 8) * ASTR + nt * 8 + 2 * tig] = pv;
                oacc[nt][hr*2+0] *= alpha;
                oacc[nt][hr*2+1] *= alpha;
            }
            psum += __shfl_xor_sync(0xffffffffu, psum, 1);
            psum += __shfl_xor_sync(0xffffffffu, psum, 2);
            l_r[hr] = l_r[hr] * alpha + psum;
            m_r[hr] = mnew;
        }
        __syncthreads();

        #pragma unroll
        for (int ks = 0; ks < 8; ++ks) {
            uint32_t pa[4];
            pa[0] = __float_as_uint(Ps[(prow    ) * ASTR + ks * 8 + tig    ]);
            pa[1] = __float_as_uint(Ps[(prow + 8) * ASTR + ks * 8 + tig    ]);
            pa[2] = __float_as_uint(Ps[(prow    ) * ASTR + ks * 8 + tig + 4]);
            pa[3] = __float_as_uint(Ps[(prow + 8) * ASTR + ks * 8 + tig + 4]);
            #pragma unroll
            for (int nt = 0; nt < 8; ++nt) {
                const int dr = nt * 8 + gid;
                const uint32_t b0 = __float_as_uint(Vt[dr * ASTR + ks * 8 + tig    ]);
                const uint32_t b1 = __float_as_uint(Vt[dr * ASTR + ks * 8 + tig + 4]);
                mma_tf32(oacc[nt][0], oacc[nt][1], oacc[nt][2], oacc[nt][3],
                         pa[0], pa[1], pa[2], pa[3], b0, b1);
            }
        }
    }

    #pragma unroll
    for (int hr = 0; hr < 2; ++hr) {
        const float inv = 1.0f / l_r[hr];
        const int token = b * SEQ + qt * 128 + wid * 16 + gid + hr * 8;
        float* orow = out + (size_t)token * EMB + h * HDIM;
        #pragma unroll
        for (int nt = 0; nt < 8; ++nt) {
            float2 ov;
            ov.x = rna_tf32_f(oacc[nt][hr*2+0] * inv);
            ov.y = rna_tf32_f(oacc[nt][hr*2+1] * inv);
            *(float2*)(orow + nt * 8 + 2 * tig) = ov;
        }
    }
}

// ---------------------------------------------------------------------------
// Launch
// ---------------------------------------------------------------------------
extern "C" void kernel_launch(void* const* d_in, const int* in_sizes, int n_in,
                              void* d_out, int out_size)
{
    (void)in_sizes; (void)n_in; (void)out_size;
    const float* x     = (const float*)d_in[0];
    const float* qkv_w = (const float*)d_in[1];
    const float* qkv_b = (const float*)d_in[2];
    const float* out_w = (const float*)d_in[3];
    const float* out_b = (const float*)d_in[4];
    const float* ff1_w = (const float*)d_in[5];
    const float* ff1_b = (const float*)d_in[6];
    const float* ff2_w = (const float*)d_in[7];
    const float* ff2_b = (const float*)d_in[8];
    const float* ln1_g = (const float*)d_in[9];
    const float* ln1_b = (const float*)d_in[10];
    const float* ln2_g = (const float*)d_in[11];
    const float* ln2_b = (const float*)d_in[12];
    float* out = (float*)d_out;

    float *bh, *bqkv, *battn, *bx1, *bff1;
    float *wqkv, *wout, *wff1, *wff2;
    cudaGetSymbolAddress((void**)&bh,    d_buf_h);
    cudaGetSymbolAddress((void**)&bqkv,  d_buf_qkv);
    cudaGetSymbolAddress((void**)&battn, d_buf_attn);
    cudaGetSymbolAddress((void**)&bx1,   d_buf_x1);
    cudaGetSymbolAddress((void**)&bff1,  d_buf_ff1);
    cudaGetSymbolAddress((void**)&wqkv,  d_w_qkv);
    cudaGetSymbolAddress((void**)&wout,  d_w_out);
    cudaGetSymbolAddress((void**)&wff1,  d_w_ff1);
    cudaGetSymbolAddress((void**)&wff2,  d_w_ff2);

    cudaFuncSetAttribute(attn_mma_kernel,
                         cudaFuncAttributeMaxDynamicSharedMemorySize, ATTN_SMEM);
    cudaFuncSetAttribute(tf32_gemm_kernel,
                         cudaFuncAttributeMaxDynamicSharedMemorySize, GEMM_SMEM);

    // 0. Pre-round weights to tf32
    {
        const int n_qkv = 3 * EMB * EMB / 4, n_out = EMB * EMB / 4;
        const int n_ff  = FFDIM * EMB / 4;
        round_kernel<<<(n_qkv + 255) / 256, 256>>>((const float4*)qkv_w, (float4*)wqkv, n_qkv);
        round_kernel<<<(n_out + 255) / 256, 256>>>((const float4*)out_w, (float4*)wout, n_out);
        round_kernel<<<(n_ff  + 255) / 256, 256>>>((const float4*)ff1_w, (float4*)wff1, n_ff);
        round_kernel<<<(n_ff  + 255) / 256, 256>>>((const float4*)ff2_w, (float4*)wff2, n_ff);
    }

    // 1. LN1 (rounded output)
    ln_kernel<<<NTOK, 256>>>(x, ln1_g, ln1_b, bh);
    // 2. QKV projection (rounded output — feeds attention)
    tf32_gemm_kernel<<<dim3(3 * EMB / 128, NTOK / 128), 256, GEMM_SMEM>>>(
        bh, wqkv, qkv_b, nullptr, bqkv, NTOK, 3 * EMB, EMB, 0);
    // 3. Attention (tensor-core flash; rounded output)
    attn_mma_kernel<<<dim3(SEQ / 128, BATCH * HEADS), 256, ATTN_SMEM>>>(bqkv, battn);
    // 4. Output projection + residual(x) — full fp32 output
    tf32_gemm_kernel<<<dim3(EMB / 128, NTOK / 128), 256, GEMM_SMEM>>>(
        battn, wout, out_b, x, bx1, NTOK, EMB, EMB, 2);
    // 5. LN2 (rounded output)
    ln_kernel<<<NTOK, 256>>>(bx1, ln2_g, ln2_b, bh);
    // 6. FF1 + GELU (rounded output)
    tf32_gemm_kernel<<<dim3(FFDIM / 128, NTOK / 128), 256, GEMM_SMEM>>>(
        bh, wff1, ff1_b, nullptr, bff1, NTOK, FFDIM, EMB, 1);
    // 7. FF2 + residual(x1) — full fp32 output
    tf32_gemm_kernel<<<dim3(EMB / 128, NTOK / 128), 256, GEMM_SMEM>>>(
        bff1, wff2, ff2_b, bx1, out, NTOK, EMB, FFDIM, 2);
}